// round 2
// baseline (speedup 1.0000x reference)
#include <cuda_runtime.h>
#include <cstdint>

// ---------------- problem constants ----------------
#define Bb 16
#define Tt 8
#define NBOX 4
#define C_IN 2048
#define C_INNER 512
#define Hh 14
#define Ww 14
#define NPIX 196          // 14*14
#define PHW 3
#define SR 2
#define NBIN 9            // 3*3
#define BT 128            // B*T
#define NROI 512          // BT*NBOX
#define ROWS_BT 36        // NBOX*NBIN
#define MBIG 4608         // NROI*NBIN
#define KFEAT 4608        // C_INNER*9
#define NCLS 174
#define NOBJ 301

#define CLS_OFF 0
#define OBJ_OFF (Bb*NCLS)                 // 2784
#define LAB_OFF (OBJ_OFF + 32*NOBJ)      // 12416

// ---------------- scratch (device globals; no runtime allocs) ----------------
__device__ float g_Wm[BT * ROWS_BT * NPIX];      // 3.6 MB
__device__ float g_ix[MBIG * C_IN];              // 37.7 MB
__device__ float g_w5t[C_IN * C_INNER];          // 4 MB   conv5_w transposed [c][o]
__device__ float g_feats[NROI * KFEAT];          // 9.4 MB
__device__ float g_reg[NROI * C_INNER];          // 1 MB (raw pre-bias sums, atomically accumulated)
__device__ float g_pooled[Bb * C_INNER];
__device__ float g_objfeas[32 * C_INNER];
__device__ float g_objh[32 * C_INNER];
__device__ float g_poolh[Bb * C_INNER];

// ---------------- K1: build interpolation weight matrix + zero g_reg ----------------
__global__ void buildW_kernel(const float* __restrict__ boxes)
{
    int bt = blockIdx.x;
    int tid = threadIdx.x;

    // zero this bt's Wm rows
    for (int idx = tid; idx < ROWS_BT * NPIX; idx += blockDim.x)
        g_Wm[bt * (ROWS_BT * NPIX) + idx] = 0.0f;

    // zero a slice of g_reg (used by split-K atomics later)
    for (int idx = tid; idx < (NROI * C_INNER) / BT; idx += blockDim.x)
        g_reg[bt * ((NROI * C_INNER) / BT) + idx] = 0.0f;

    __syncthreads();

    if (tid < ROWS_BT) {
        int r   = tid;
        int box = r / NBIN;
        int bin = r % NBIN;
        int py  = bin / PHW;
        int px  = bin % PHW;

        const float* bp = &boxes[(bt * NBOX + box) * 4];
        float cx = bp[0], cy = bp[1], w = bp[2], h = bp[3];
        const float scale = (float)Hh / 224.0f;
        float x1 = ((cx - 0.5f * w) * 224.0f) * scale;
        float y1 = ((cy - 0.5f * h) * 224.0f) * scale;
        float x2 = ((cx + 0.5f * w) * 224.0f) * scale;
        float y2 = ((cy + 0.5f * h) * 224.0f) * scale;

        float roi_w = fmaxf(x2 - x1, 1.0f);
        float roi_h = fmaxf(y2 - y1, 1.0f);
        float bw = roi_w / (float)PHW;
        float bh = roi_h / (float)PHW;

        float* row = &g_Wm[(bt * ROWS_BT + r) * NPIX];

        #pragma unroll
        for (int jy = 0; jy < SR; jy++) {
            float yy = y1 + (float)py * bh + ((float)jy + 0.5f) * bh / (float)SR;
            #pragma unroll
            for (int jx = 0; jx < SR; jx++) {
                float xx = x1 + (float)px * bw + ((float)jx + 0.5f) * bw / (float)SR;
                bool valid = (yy > -1.0f) && (yy < (float)Hh) && (xx > -1.0f) && (xx < (float)Ww);
                if (!valid) continue;
                float y = fminf(fmaxf(yy, 0.0f), (float)(Hh - 1));
                float x = fminf(fmaxf(xx, 0.0f), (float)(Ww - 1));
                int y0 = (int)floorf(y);
                int x0 = (int)floorf(x);
                int y1i = min(y0 + 1, Hh - 1);
                int x1i = min(x0 + 1, Ww - 1);
                float ly = y - (float)y0, lx = x - (float)x0;
                float hy = 1.0f - ly,     hx = 1.0f - lx;
                row[y0 * Ww + x0]   += hy * hx * 0.25f;
                row[y0 * Ww + x1i]  += hy * lx * 0.25f;
                row[y1i * Ww + x0]  += ly * hx * 0.25f;
                row[y1i * Ww + x1i] += ly * lx * 0.25f;
            }
        }
    }
}

// ---------------- K2: ix[bt*36+r][c] = sum_p Wm[bt][r][p] * x[b][c][t][p] ----------------
// grid = (16 ctiles, 128 bt), block = 128 threads, dynamic smem
#define XS_PITCH 204   // 196 padded; 51 float4 -> odd stride, conflict-free
__global__ void interp_kernel(const float* __restrict__ x)
{
    extern __shared__ float smem[];
    float* ws = smem;                    // [36][196]
    float* xs = smem + ROWS_BT * NPIX;   // [128][XS_PITCH]

    int bt = blockIdx.y;
    int c0 = blockIdx.x * 128;
    int b  = bt >> 3;
    int t  = bt & 7;
    int tid  = threadIdx.x;
    int lane = tid & 31;
    int rg   = tid >> 5;     // 0..3 -> 9 rows each

    for (int idx = tid; idx < ROWS_BT * NPIX; idx += 128)
        ws[idx] = g_Wm[bt * (ROWS_BT * NPIX) + idx];

    for (int idx = tid; idx < 128 * NPIX; idx += 128) {
        int c = idx / NPIX;
        int p = idx % NPIX;
        xs[c * XS_PITCH + p] = x[((size_t)((b * C_IN + c0 + c) * Tt + t)) * NPIX + p];
    }
    __syncthreads();

    float acc[9][4];
    #pragma unroll
    for (int i = 0; i < 9; i++)
        #pragma unroll
        for (int j = 0; j < 4; j++) acc[i][j] = 0.0f;

    for (int p4 = 0; p4 < NPIX / 4; p4++) {
        float4 xv[4];
        #pragma unroll
        for (int j = 0; j < 4; j++)
            xv[j] = *(const float4*)&xs[(j * 32 + lane) * XS_PITCH + p4 * 4];
        #pragma unroll
        for (int i = 0; i < 9; i++) {
            float4 wv = *(const float4*)&ws[(rg * 9 + i) * NPIX + p4 * 4];
            #pragma unroll
            for (int j = 0; j < 4; j++) {
                acc[i][j] += wv.x * xv[j].x;
                acc[i][j] += wv.y * xv[j].y;
                acc[i][j] += wv.z * xv[j].z;
                acc[i][j] += wv.w * xv[j].w;
            }
        }
    }

    #pragma unroll
    for (int i = 0; i < 9; i++) {
        int m = bt * ROWS_BT + rg * 9 + i;
        #pragma unroll
        for (int j = 0; j < 4; j++)
            g_ix[(size_t)m * C_IN + c0 + j * 32 + lane] = acc[i][j];
    }
}

// ---------------- transpose conv5_w (512x2048 -> 2048x512) ----------------
__global__ void transpose_w5(const float* __restrict__ wsrc)
{
    __shared__ float tile[32][33];
    int c0 = blockIdx.x * 32;
    int o0 = blockIdx.y * 32;
    int tx = threadIdx.x, ty = threadIdx.y;
    for (int i = ty; i < 32; i += 8)
        tile[i][tx] = wsrc[(size_t)(o0 + i) * C_IN + c0 + tx];
    __syncthreads();
    for (int i = ty; i < 32; i += 8)
        g_w5t[(size_t)(c0 + i) * C_INNER + o0 + tx] = tile[tx][i];
}

// ---------------- SGEMM: C = A(MxK, K-contig) @ W(KxN, N-contig) ----------------
// MODE 1: scatter into feats layout. MODE 2: atomicAdd into C (split-K).
template <int MODE>
__global__ __launch_bounds__(256) void sgemm128(const float* __restrict__ A,
                                                const float* __restrict__ Bw,
                                                float* __restrict__ C,
                                                int M, int N, int K, int kSplit)
{
    __shared__ float As[16 * 128];
    __shared__ float Bs[16 * 128];

    int tid = threadIdx.x;
    int tx = tid & 15;
    int ty = tid >> 4;
    int n0 = blockIdx.x * 128;
    int m0 = blockIdx.y * 128;
    int kLen = K / kSplit;
    int k0 = blockIdx.z * kLen;

    float acc[8][8];
    #pragma unroll
    for (int i = 0; i < 8; i++)
        #pragma unroll
        for (int j = 0; j < 8; j++) acc[i][j] = 0.0f;

    for (int kt = 0; kt < kLen; kt += 16) {
        #pragma unroll
        for (int u = 0; u < 2; u++) {
            int idx = tid * 2 + u;              // 0..511
            int m  = idx >> 2, kq = idx & 3;
            float4 av = *(const float4*)&A[(size_t)(m0 + m) * K + k0 + kt + kq * 4];
            As[(kq * 4 + 0) * 128 + m] = av.x;
            As[(kq * 4 + 1) * 128 + m] = av.y;
            As[(kq * 4 + 2) * 128 + m] = av.z;
            As[(kq * 4 + 3) * 128 + m] = av.w;
            int kb = idx >> 5, nq = idx & 31;
            float4 bv = *(const float4*)&Bw[(size_t)(k0 + kt + kb) * N + n0 + nq * 4];
            *(float4*)&Bs[kb * 128 + nq * 4] = bv;
        }
        __syncthreads();
        #pragma unroll
        for (int k = 0; k < 16; k++) {
            float4 a0 = *(const float4*)&As[k * 128 + ty * 8];
            float4 a1 = *(const float4*)&As[k * 128 + ty * 8 + 4];
            float4 b0 = *(const float4*)&Bs[k * 128 + tx * 8];
            float4 b1 = *(const float4*)&Bs[k * 128 + tx * 8 + 4];
            float av[8] = {a0.x, a0.y, a0.z, a0.w, a1.x, a1.y, a1.z, a1.w};
            float bv[8] = {b0.x, b0.y, b0.z, b0.w, b1.x, b1.y, b1.z, b1.w};
            #pragma unroll
            for (int i = 0; i < 8; i++)
                #pragma unroll
                for (int j = 0; j < 8; j++)
                    acc[i][j] += av[i] * bv[j];
        }
        __syncthreads();
    }

    #pragma unroll
    for (int i = 0; i < 8; i++) {
        int m = m0 + ty * 8 + i;
        #pragma unroll
        for (int j = 0; j < 8; j++) {
            int n = n0 + tx * 8 + j;
            if (MODE == 1) {
                // cf[m][n] -> feats[m/9][n*9 + m%9]
                g_feats[(size_t)(m / 9) * KFEAT + n * 9 + (m % 9)] = acc[i][j];
            } else if (MODE == 2) {
                atomicAdd(&C[(size_t)m * N + n], acc[i][j]);
            } else {
                C[(size_t)m * N + n] = acc[i][j];
            }
        }
    }
}

// ---------------- fused bias+ReLU+means+obj-gather ----------------
__global__ void meanhead_kernel(const float* __restrict__ re_b,
                                const int* __restrict__ obj_cat,
                                float* __restrict__ d_out_lab)
{
    int b = blockIdx.x;
    int o = threadIdx.x;   // 512
    float rb = re_b[o];

    float rm[4];
    #pragma unroll
    for (int box = 0; box < 4; box++) {
        float s = 0.0f;
        #pragma unroll
        for (int t = 0; t < 8; t++) {
            float v = g_reg[(size_t)(((b * 8 + t) * 4 + box)) * C_INNER + o] + rb;
            s += fmaxf(v, 0.0f);
        }
        rm[box] = s * 0.125f;
    }
    g_pooled[b * C_INNER + o] = (rm[0] + rm[1] + rm[2] + rm[3]) * 0.25f;

    int c2 = obj_cat[b * 4 + 2];
    int c3 = obj_cat[b * 4 + 3];
    int i0 = 0, i1 = 1;
    if (c2 == 0 && c3 != 0) { i0 = 1; i1 = 0; }   // stable argsort of (==0) flags
    g_objfeas[(size_t)(b * 2 + 0) * C_INNER + o] = rm[2 + i0];
    g_objfeas[(size_t)(b * 2 + 1) * C_INNER + o] = rm[2 + i1];
    if (o == 0) {
        d_out_lab[b * 2 + 0] = (float)(i0 ? c3 : c2);
        d_out_lab[b * 2 + 1] = (float)(i1 ? c3 : c2);
    }
}

// ---------------- small FC: out = A(MxK) @ W(KxN) + bias ----------------
// grid (ceil(N/128), M/8), block 128
__global__ void small_nn(const float* __restrict__ A, const float* __restrict__ W,
                         const float* __restrict__ bias, float* __restrict__ out,
                         int M, int N, int K)
{
    __shared__ float As[8 * 512];
    int r0 = blockIdx.y * 8;
    int tid = threadIdx.x;
    for (int idx = tid; idx < 8 * K; idx += blockDim.x)
        As[idx] = A[(size_t)(r0 + idx / K) * K + (idx % K)];
    __syncthreads();

    int n = blockIdx.x * blockDim.x + tid;
    if (n >= N) return;

    float acc[8];
    float bv = bias[n];
    #pragma unroll
    for (int m = 0; m < 8; m++) acc[m] = bv;

    for (int k4 = 0; k4 < K / 4; k4++) {
        float w0 = W[(size_t)(k4 * 4 + 0) * N + n];
        float w1 = W[(size_t)(k4 * 4 + 1) * N + n];
        float w2 = W[(size_t)(k4 * 4 + 2) * N + n];
        float w3 = W[(size_t)(k4 * 4 + 3) * N + n];
        #pragma unroll
        for (int m = 0; m < 8; m++) {
            float4 a = *(const float4*)&As[m * K + k4 * 4];
            acc[m] += a.x * w0 + a.y * w1 + a.z * w2 + a.w * w3;
        }
    }
    #pragma unroll
    for (int m = 0; m < 8; m++)
        out[(size_t)(r0 + m) * N + n] = acc[m];
}

// ---------------- launch ----------------
extern "C" void kernel_launch(void* const* d_in, const int* in_sizes, int n_in,
                              void* d_out, int out_size)
{
    const float* x       = (const float*)d_in[0];
    const float* boxes   = (const float*)d_in[1];
    const int*   cat     = (const int*)d_in[2];
    const float* conv5_w = (const float*)d_in[3];
    const float* re_w    = (const float*)d_in[4];
    const float* re_b    = (const float*)d_in[5];
    const float* oc1_w   = (const float*)d_in[6];
    const float* oc1_b   = (const float*)d_in[7];
    const float* oc2_w   = (const float*)d_in[8];
    const float* oc2_b   = (const float*)d_in[9];
    const float* pr1_w   = (const float*)d_in[10];
    const float* pr1_b   = (const float*)d_in[11];
    const float* pr2_w   = (const float*)d_in[12];
    const float* pr2_b   = (const float*)d_in[13];
    float* out = (float*)d_out;

    // symbol addresses (host API, capture-safe)
    float *p_ix, *p_w5t, *p_feats, *p_reg, *p_pooled, *p_objfeas, *p_objh, *p_poolh;
    cudaGetSymbolAddress((void**)&p_ix, g_ix);
    cudaGetSymbolAddress((void**)&p_w5t, g_w5t);
    cudaGetSymbolAddress((void**)&p_feats, g_feats);
    cudaGetSymbolAddress((void**)&p_reg, g_reg);
    cudaGetSymbolAddress((void**)&p_pooled, g_pooled);
    cudaGetSymbolAddress((void**)&p_objfeas, g_objfeas);
    cudaGetSymbolAddress((void**)&p_objh, g_objh);
    cudaGetSymbolAddress((void**)&p_poolh, g_poolh);

    // K2 needs ~133 KB dynamic smem
    size_t smemK2 = (size_t)(ROWS_BT * NPIX + 128 * XS_PITCH) * sizeof(float);
    cudaFuncSetAttribute(interp_kernel, cudaFuncAttributeMaxDynamicSharedMemorySize, (int)smemK2);

    // K1: build W matrices (+ zero g_reg)
    buildW_kernel<<<BT, 256>>>(boxes);

    // transpose conv5_w -> [c][o]
    transpose_w5<<<dim3(C_IN / 32, C_INNER / 32), dim3(32, 8)>>>(conv5_w);

    // K2: ix = Wm @ X^T  (batched over bt)
    interp_kernel<<<dim3(C_IN / 128, BT), 128, smemK2>>>(x);

    // G1: cf = ix(4608x2048) @ w5t(2048x512), scattered into feats layout
    sgemm128<1><<<dim3(C_INNER / 128, MBIG / 128, 1), 256>>>(p_ix, p_w5t, p_feats,
                                                             MBIG, C_INNER, C_IN, 1);

    // G2: reg_raw = feats(512x4608) @ re_w(4608x512), split-K=8 atomic
    sgemm128<2><<<dim3(C_INNER / 128, NROI / 128, 8), 256>>>(p_feats, re_w, p_reg,
                                                              NROI, C_INNER, KFEAT, 8);

    // bias+relu+means+obj gather; labels written directly
    meanhead_kernel<<<Bb, C_INNER>>>(re_b, cat, out + LAB_OFF);

    // obj head: (32x512)@(512x512)+b -> (32x512)@(512x301)+b -> d_out
    small_nn<<<dim3(4, 4), 128>>>(p_objfeas, oc1_w, oc1_b, p_objh, 32, C_INNER, C_INNER);
    small_nn<<<dim3((NOBJ + 127) / 128, 4), 128>>>(p_objh, oc2_w, oc2_b, out + OBJ_OFF,
                                                    32, NOBJ, C_INNER);

    // cls head: (16x512)@(512x512)+b -> (16x512)@(512x174)+b -> d_out
    small_nn<<<dim3(4, 2), 128>>>(p_pooled, pr1_w, pr1_b, p_poolh, Bb, C_INNER, C_INNER);
    small_nn<<<dim3((NCLS + 127) / 128, 2), 128>>>(p_poolh, pr2_w, pr2_b, out + CLS_OFF,
                                                    Bb, NCLS, C_INNER);
}

// round 3
// speedup vs baseline: 1.6242x; 1.6242x over previous
#include <cuda_runtime.h>
#include <cstdint>

// ---------------- problem constants ----------------
#define Bb 16
#define Tt 8
#define NBOX 4
#define C_IN 2048
#define C_INNER 512
#define Hh 14
#define Ww 14
#define NPIX 196          // 14*14
#define PHW 3
#define SR 2
#define NBIN 9            // 3*3
#define BT 128            // B*T
#define NROI 512          // BT*NBOX
#define ROWS_BT 36        // NBOX*NBIN
#define MBIG 4608         // NROI*NBIN
#define KFEAT 4608        // C_INNER*9
#define NCLS 174
#define NOBJ 301

#define CLS_OFF 0
#define OBJ_OFF (Bb*NCLS)                 // 2784
#define LAB_OFF (OBJ_OFF + 32*NOBJ)      // 12416

// ---------------- scratch (device globals; no runtime allocs) ----------------
__device__ float g_Wm[BT * ROWS_BT * NPIX];      // 3.6 MB
__device__ float g_ix[MBIG * C_IN];              // 37.7 MB
__device__ float g_feats[NROI * KFEAT];          // 9.4 MB
__device__ float g_reg[NROI * C_INNER];          // 1 MB (split-K atomic accum)
__device__ float g_pooled[Bb * C_INNER];
__device__ float g_objfeas[32 * C_INNER];
__device__ float g_objh[32 * C_INNER];
__device__ float g_poolh[Bb * C_INNER];

// ---------------- tf32 helpers ----------------
__device__ __forceinline__ void split_tf32(float f, uint32_t& hi, uint32_t& lo)
{
    asm("cvt.rna.tf32.f32 %0, %1;" : "=r"(hi) : "f"(f));
    float r = f - __uint_as_float(hi);
    asm("cvt.rna.tf32.f32 %0, %1;" : "=r"(lo) : "f"(r));
}

__device__ __forceinline__ void mma_tf32(float* c, const uint32_t* a, const uint32_t* b)
{
    asm volatile(
        "mma.sync.aligned.m16n8k8.row.col.f32.tf32.tf32.f32 "
        "{%0,%1,%2,%3}, {%4,%5,%6,%7}, {%8,%9}, {%0,%1,%2,%3};"
        : "+f"(c[0]), "+f"(c[1]), "+f"(c[2]), "+f"(c[3])
        : "r"(a[0]), "r"(a[1]), "r"(a[2]), "r"(a[3]), "r"(b[0]), "r"(b[1]));
}

// ---------------- K1: build interpolation weight matrix + zero g_reg ----------------
__global__ void buildW_kernel(const float* __restrict__ boxes)
{
    int bt = blockIdx.x;
    int tid = threadIdx.x;

    for (int idx = tid; idx < ROWS_BT * NPIX; idx += blockDim.x)
        g_Wm[bt * (ROWS_BT * NPIX) + idx] = 0.0f;

    for (int idx = tid; idx < (NROI * C_INNER) / BT; idx += blockDim.x)
        g_reg[bt * ((NROI * C_INNER) / BT) + idx] = 0.0f;

    __syncthreads();

    if (tid < ROWS_BT) {
        int r   = tid;
        int box = r / NBIN;
        int bin = r % NBIN;
        int py  = bin / PHW;
        int px  = bin % PHW;

        const float* bp = &boxes[(bt * NBOX + box) * 4];
        float cx = bp[0], cy = bp[1], w = bp[2], h = bp[3];
        const float scale = (float)Hh / 224.0f;
        float x1 = ((cx - 0.5f * w) * 224.0f) * scale;
        float y1 = ((cy - 0.5f * h) * 224.0f) * scale;
        float x2 = ((cx + 0.5f * w) * 224.0f) * scale;
        float y2 = ((cy + 0.5f * h) * 224.0f) * scale;

        float roi_w = fmaxf(x2 - x1, 1.0f);
        float roi_h = fmaxf(y2 - y1, 1.0f);
        float bw = roi_w / (float)PHW;
        float bh = roi_h / (float)PHW;

        float* row = &g_Wm[(bt * ROWS_BT + r) * NPIX];

        #pragma unroll
        for (int jy = 0; jy < SR; jy++) {
            float yy = y1 + (float)py * bh + ((float)jy + 0.5f) * bh / (float)SR;
            #pragma unroll
            for (int jx = 0; jx < SR; jx++) {
                float xx = x1 + (float)px * bw + ((float)jx + 0.5f) * bw / (float)SR;
                bool valid = (yy > -1.0f) && (yy < (float)Hh) && (xx > -1.0f) && (xx < (float)Ww);
                if (!valid) continue;
                float y = fminf(fmaxf(yy, 0.0f), (float)(Hh - 1));
                float x = fminf(fmaxf(xx, 0.0f), (float)(Ww - 1));
                int y0 = (int)floorf(y);
                int x0 = (int)floorf(x);
                int y1i = min(y0 + 1, Hh - 1);
                int x1i = min(x0 + 1, Ww - 1);
                float ly = y - (float)y0, lx = x - (float)x0;
                float hy = 1.0f - ly,     hx = 1.0f - lx;
                row[y0 * Ww + x0]   += hy * hx * 0.25f;
                row[y0 * Ww + x1i]  += hy * lx * 0.25f;
                row[y1i * Ww + x0]  += ly * hx * 0.25f;
                row[y1i * Ww + x1i] += ly * lx * 0.25f;
            }
        }
    }
}

// ---------------- K2: ix[bt*36+r][c] = sum_p Wm[bt][r][p] * x[b][c][t][p] ----------------
// grid = (16 ctiles, 128 bt), block = 256 threads (8 warps), dynamic smem
#define XS_P4 51   // pitch in float4 units (= 204 floats, odd stride)
__global__ __launch_bounds__(256) void interp_kernel(const float* __restrict__ x)
{
    extern __shared__ float smem[];
    float*  ws  = smem;                                  // [36][196]
    float4* ws4 = (float4*)ws;                           // [36][49]
    float4* xs4 = (float4*)(smem + ROWS_BT * NPIX);      // [128][51]

    int bt = blockIdx.y;
    int c0 = blockIdx.x * 128;
    int b  = bt >> 3;
    int t  = bt & 7;
    int tid = threadIdx.x;

    for (int idx = tid; idx < ROWS_BT * NPIX; idx += 256)
        ws[idx] = g_Wm[bt * (ROWS_BT * NPIX) + idx];

    const float4* xg = (const float4*)(x + ((size_t)(b * C_IN + c0) * Tt + t) * NPIX);
    // stride between channels in float4: Tt*NPIX/4 = 392
    for (int idx = tid; idx < 128 * 49; idx += 256) {
        int c = idx / 49, p4 = idx % 49;
        xs4[c * XS_P4 + p4] = xg[(size_t)c * 392 + p4];
    }
    __syncthreads();

    int lane = tid & 31;
    int rg   = (tid >> 5) & 3;   // 0..3 -> rows rg*9..rg*9+8
    int ch   = tid >> 7;         // 0/1 -> channel halves
    int cA   = ch * 64 + lane;
    int cB   = cA + 32;

    float acc[9][2];
    #pragma unroll
    for (int i = 0; i < 9; i++) { acc[i][0] = 0.0f; acc[i][1] = 0.0f; }

    for (int p4 = 0; p4 < 49; p4++) {
        float4 xa = xs4[cA * XS_P4 + p4];
        float4 xb = xs4[cB * XS_P4 + p4];
        #pragma unroll
        for (int i = 0; i < 9; i++) {
            float4 wv = ws4[(rg * 9 + i) * 49 + p4];
            acc[i][0] += wv.x * xa.x; acc[i][0] += wv.y * xa.y;
            acc[i][0] += wv.z * xa.z; acc[i][0] += wv.w * xa.w;
            acc[i][1] += wv.x * xb.x; acc[i][1] += wv.y * xb.y;
            acc[i][1] += wv.z * xb.z; acc[i][1] += wv.w * xb.w;
        }
    }

    #pragma unroll
    for (int i = 0; i < 9; i++) {
        int m = bt * ROWS_BT + rg * 9 + i;
        g_ix[(size_t)m * C_IN + c0 + cA] = acc[i][0];
        g_ix[(size_t)m * C_IN + c0 + cB] = acc[i][1];
    }
}

// ---------------- tensor-core GEMM (3xTF32 split): C = A(MxK) @ B ----------------
// BKMAJ=1: B stored [n][k] (k-contig, e.g. conv5_w).  BKMAJ=0: B stored [k][n].
// MODE=1: scatter into g_feats layout.  MODE=2: atomicAdd into C (split-K).
// Block tile 128x128x16, 256 threads (8 warps as 2x4), warp tile 64x32.
#define SP 136   // smem pitch (floats): 136 mod 32 = 8 -> conflict-free frag loads
template <int MODE, int BKMAJ>
__global__ __launch_bounds__(256) void gemm_tc(const float* __restrict__ A,
                                               const float* __restrict__ Bw,
                                               float* __restrict__ C,
                                               int M, int N, int K, int kSplit)
{
    __shared__ float As[16][SP];
    __shared__ float Bs[16][SP];

    int tid  = threadIdx.x;
    int lane = tid & 31, wid = tid >> 5;
    int wm = (wid & 1) * 64;
    int wn = (wid >> 1) * 32;
    int gid = lane >> 2, tig = lane & 3;
    int n0 = blockIdx.x * 128;
    int m0 = blockIdx.y * 128;
    int kLen = K / kSplit;
    int k0base = blockIdx.z * kLen;
    int iters = kLen / 16;

    float acc[4][4][4];
    #pragma unroll
    for (int a = 0; a < 4; a++)
        #pragma unroll
        for (int bq = 0; bq < 4; bq++)
            #pragma unroll
            for (int cq = 0; cq < 4; cq++) acc[a][bq][cq] = 0.0f;

    float4 rA[2], rB[2];

    auto ldg = [&](int kt) {
        int kk = k0base + kt * 16;
        #pragma unroll
        for (int f = 0; f < 2; f++) {
            int idx = tid * 2 + f;
            rA[f] = *(const float4*)&A[(size_t)(m0 + (idx >> 2)) * K + kk + (idx & 3) * 4];
            if (BKMAJ)
                rB[f] = *(const float4*)&Bw[(size_t)(n0 + (idx >> 2)) * K + kk + (idx & 3) * 4];
            else
                rB[f] = *(const float4*)&Bw[(size_t)(kk + (idx >> 5)) * N + n0 + (idx & 31) * 4];
        }
    };

    auto sts = [&]() {
        #pragma unroll
        for (int f = 0; f < 2; f++) {
            int idx = tid * 2 + f;
            int r = idx >> 2, kq = idx & 3;
            As[kq * 4 + 0][r] = rA[f].x;
            As[kq * 4 + 1][r] = rA[f].y;
            As[kq * 4 + 2][r] = rA[f].z;
            As[kq * 4 + 3][r] = rA[f].w;
            if (BKMAJ) {
                Bs[kq * 4 + 0][r] = rB[f].x;
                Bs[kq * 4 + 1][r] = rB[f].y;
                Bs[kq * 4 + 2][r] = rB[f].z;
                Bs[kq * 4 + 3][r] = rB[f].w;
            } else {
                int bk = idx >> 5, nq = idx & 31;
                *(float4*)&Bs[bk][nq * 4] = rB[f];
            }
        }
    };

    ldg(0);
    for (int kt = 0; kt < iters; kt++) {
        sts();
        __syncthreads();
        if (kt + 1 < iters) ldg(kt + 1);

        #pragma unroll
        for (int ks = 0; ks < 2; ks++) {
            int kk = ks * 8;
            uint32_t bhi[4][2], blo[4][2];
            #pragma unroll
            for (int na = 0; na < 4; na++) {
                split_tf32(Bs[kk + tig][wn + na * 8 + gid],     bhi[na][0], blo[na][0]);
                split_tf32(Bs[kk + tig + 4][wn + na * 8 + gid], bhi[na][1], blo[na][1]);
            }
            #pragma unroll
            for (int ma = 0; ma < 4; ma++) {
                uint32_t ahi[4], alo[4];
                int mb = wm + ma * 16 + gid;
                split_tf32(As[kk + tig][mb],         ahi[0], alo[0]);
                split_tf32(As[kk + tig][mb + 8],     ahi[1], alo[1]);
                split_tf32(As[kk + tig + 4][mb],     ahi[2], alo[2]);
                split_tf32(As[kk + tig + 4][mb + 8], ahi[3], alo[3]);
                #pragma unroll
                for (int na = 0; na < 4; na++) {
                    mma_tf32(acc[ma][na], alo, bhi[na]);
                    mma_tf32(acc[ma][na], ahi, blo[na]);
                    mma_tf32(acc[ma][na], ahi, bhi[na]);
                }
            }
        }
        __syncthreads();
    }

    // epilogue
    #pragma unroll
    for (int ma = 0; ma < 4; ma++) {
        #pragma unroll
        for (int na = 0; na < 4; na++) {
            int mr = m0 + wm + ma * 16 + gid;
            int nc = n0 + wn + na * 8 + tig * 2;
            float* cc = acc[ma][na];
            if (MODE == 1) {
                int mr2 = mr + 8;
                g_feats[(size_t)(mr  / 9) * KFEAT + nc       * 9 + (mr  % 9)] = cc[0];
                g_feats[(size_t)(mr  / 9) * KFEAT + (nc + 1) * 9 + (mr  % 9)] = cc[1];
                g_feats[(size_t)(mr2 / 9) * KFEAT + nc       * 9 + (mr2 % 9)] = cc[2];
                g_feats[(size_t)(mr2 / 9) * KFEAT + (nc + 1) * 9 + (mr2 % 9)] = cc[3];
            } else {
                atomicAdd(&C[(size_t)mr * N + nc],           cc[0]);
                atomicAdd(&C[(size_t)mr * N + nc + 1],       cc[1]);
                atomicAdd(&C[(size_t)(mr + 8) * N + nc],     cc[2]);
                atomicAdd(&C[(size_t)(mr + 8) * N + nc + 1], cc[3]);
            }
        }
    }
}

// ---------------- fused bias+ReLU+means+obj-gather ----------------
__global__ void meanhead_kernel(const float* __restrict__ re_b,
                                const int* __restrict__ obj_cat,
                                float* __restrict__ d_out_lab)
{
    int b = blockIdx.x;
    int o = threadIdx.x;   // 512
    float rb = re_b[o];

    float rm[4];
    #pragma unroll
    for (int box = 0; box < 4; box++) {
        float s = 0.0f;
        #pragma unroll
        for (int t = 0; t < 8; t++) {
            float v = g_reg[(size_t)(((b * 8 + t) * 4 + box)) * C_INNER + o] + rb;
            s += fmaxf(v, 0.0f);
        }
        rm[box] = s * 0.125f;
    }
    g_pooled[b * C_INNER + o] = (rm[0] + rm[1] + rm[2] + rm[3]) * 0.25f;

    int c2 = obj_cat[b * 4 + 2];
    int c3 = obj_cat[b * 4 + 3];
    int i0 = 0, i1 = 1;
    if (c2 == 0 && c3 != 0) { i0 = 1; i1 = 0; }   // stable argsort of (==0) flags
    g_objfeas[(size_t)(b * 2 + 0) * C_INNER + o] = rm[2 + i0];
    g_objfeas[(size_t)(b * 2 + 1) * C_INNER + o] = rm[2 + i1];
    if (o == 0) {
        d_out_lab[b * 2 + 0] = (float)(i0 ? c3 : c2);
        d_out_lab[b * 2 + 1] = (float)(i1 ? c3 : c2);
    }
}

// ---------------- small FC: out = A(MxK) @ W(KxN) + bias ----------------
__global__ void small_nn(const float* __restrict__ A, const float* __restrict__ W,
                         const float* __restrict__ bias, float* __restrict__ out,
                         int M, int N, int K)
{
    __shared__ float As[8 * 512];
    int r0 = blockIdx.y * 8;
    int tid = threadIdx.x;
    for (int idx = tid; idx < 8 * K; idx += blockDim.x)
        As[idx] = A[(size_t)(r0 + idx / K) * K + (idx % K)];
    __syncthreads();

    int n = blockIdx.x * blockDim.x + tid;
    if (n >= N) return;

    float acc[8];
    float bv = bias[n];
    #pragma unroll
    for (int m = 0; m < 8; m++) acc[m] = bv;

    for (int k4 = 0; k4 < K / 4; k4++) {
        float w0 = W[(size_t)(k4 * 4 + 0) * N + n];
        float w1 = W[(size_t)(k4 * 4 + 1) * N + n];
        float w2 = W[(size_t)(k4 * 4 + 2) * N + n];
        float w3 = W[(size_t)(k4 * 4 + 3) * N + n];
        #pragma unroll
        for (int m = 0; m < 8; m++) {
            float4 a = *(const float4*)&As[m * K + k4 * 4];
            acc[m] += a.x * w0 + a.y * w1 + a.z * w2 + a.w * w3;
        }
    }
    #pragma unroll
    for (int m = 0; m < 8; m++)
        out[(size_t)(r0 + m) * N + n] = acc[m];
}

// ---------------- launch ----------------
extern "C" void kernel_launch(void* const* d_in, const int* in_sizes, int n_in,
                              void* d_out, int out_size)
{
    const float* x       = (const float*)d_in[0];
    const float* boxes   = (const float*)d_in[1];
    const int*   cat     = (const int*)d_in[2];
    const float* conv5_w = (const float*)d_in[3];
    const float* re_w    = (const float*)d_in[4];
    const float* re_b    = (const float*)d_in[5];
    const float* oc1_w   = (const float*)d_in[6];
    const float* oc1_b   = (const float*)d_in[7];
    const float* oc2_w   = (const float*)d_in[8];
    const float* oc2_b   = (const float*)d_in[9];
    const float* pr1_w   = (const float*)d_in[10];
    const float* pr1_b   = (const float*)d_in[11];
    const float* pr2_w   = (const float*)d_in[12];
    const float* pr2_b   = (const float*)d_in[13];
    float* out = (float*)d_out;

    float *p_ix, *p_feats, *p_reg, *p_pooled, *p_objfeas, *p_objh, *p_poolh;
    cudaGetSymbolAddress((void**)&p_ix, g_ix);
    cudaGetSymbolAddress((void**)&p_feats, g_feats);
    cudaGetSymbolAddress((void**)&p_reg, g_reg);
    cudaGetSymbolAddress((void**)&p_pooled, g_pooled);
    cudaGetSymbolAddress((void**)&p_objfeas, g_objfeas);
    cudaGetSymbolAddress((void**)&p_objh, g_objh);
    cudaGetSymbolAddress((void**)&p_poolh, g_poolh);

    size_t smemK2 = (size_t)(ROWS_BT * NPIX + 128 * (XS_P4 * 4)) * sizeof(float);
    cudaFuncSetAttribute(interp_kernel, cudaFuncAttributeMaxDynamicSharedMemorySize, (int)smemK2);

    // K1: build interpolation matrices + zero g_reg
    buildW_kernel<<<BT, 256>>>(boxes);

    // K2: ix = Wm @ X^T  (batched over bt)
    interp_kernel<<<dim3(C_IN / 128, BT), 256, smemK2>>>(x);

    // G1: cf = ix(4608x2048) @ conv5_w^T(2048x512)  [B is (512x2048) k-major]
    //     scattered into feats layout, 3xTF32 tensor cores
    gemm_tc<1, 1><<<dim3(C_INNER / 128, MBIG / 128, 1), 256>>>(p_ix, conv5_w, p_feats,
                                                               MBIG, C_INNER, C_IN, 1);

    // G2: reg_raw = feats(512x4608) @ re_w(4608x512), split-K=8 atomic, 3xTF32
    gemm_tc<2, 0><<<dim3(C_INNER / 128, NROI / 128, 8), 256>>>(p_feats, re_w, p_reg,
                                                               NROI, C_INNER, KFEAT, 8);

    // bias+relu+means+obj gather; labels written directly
    meanhead_kernel<<<Bb, C_INNER>>>(re_b, cat, out + LAB_OFF);

    // obj head: (32x512)@(512x512)+b -> (32x512)@(512x301)+b -> d_out
    small_nn<<<dim3(4, 4), 128>>>(p_objfeas, oc1_w, oc1_b, p_objh, 32, C_INNER, C_INNER);
    small_nn<<<dim3((NOBJ + 127) / 128, 4), 128>>>(p_objh, oc2_w, oc2_b, out + OBJ_OFF,
                                                    32, NOBJ, C_INNER);

    // cls head: (16x512)@(512x512)+b -> (16x512)@(512x174)+b -> d_out
    small_nn<<<dim3(4, 2), 128>>>(p_pooled, pr1_w, pr1_b, p_poolh, Bb, C_INNER, C_INNER);
    small_nn<<<dim3((NCLS + 127) / 128, 2), 128>>>(p_poolh, pr2_w, pr2_b, out + CLS_OFF,
                                                    Bb, NCLS, C_INNER);
}